// round 2
// baseline (speedup 1.0000x reference)
#include <cuda_runtime.h>

#define NNEI 128
#define NG2  32
#define ND   32
#define NH   4
#define THREADS 256

#define ATTNW_SHIFT 20.0f
#define INV_SQRT_D  0.17677669529663687f   // 1/sqrt(32)
#define SQRT3       1.7320508075688772f

struct Smem {
    float wqkT[256][32];   // transposed w_qk: [j][c], j = d*8 + head_slot
    float wvT[128][32];    // transposed w_v:  [j][c], j = g*4 + h
    float wh[128][32];     // w_head natural [m][j]
    float K[128][36];      // K rows for current head (stride 36 = 4 banks)
    float V[128][36];      // V rows for current head
    float A[128 * 130];    // logits/exp rows; stride 130 (== 2 mod 32) -> conflict-free
    float h2s[128][4];
    float sw[128];
    float swm[128];        // sw * mask
    float bh[32];
    float weq[4];
};

__device__ __forceinline__ float dot32(const float* a, const float* w) {
    const float4* w4 = reinterpret_cast<const float4*>(w);
    float s0 = 0.f, s1 = 0.f, s2 = 0.f, s3 = 0.f;
    float4 x0 = w4[0], x1 = w4[1], x2 = w4[2], x3 = w4[3];
    s0 = fmaf(a[0],  x0.x, s0); s0 = fmaf(a[1],  x0.y, s0);
    s0 = fmaf(a[2],  x0.z, s0); s0 = fmaf(a[3],  x0.w, s0);
    s1 = fmaf(a[4],  x1.x, s1); s1 = fmaf(a[5],  x1.y, s1);
    s1 = fmaf(a[6],  x1.z, s1); s1 = fmaf(a[7],  x1.w, s1);
    s2 = fmaf(a[8],  x2.x, s2); s2 = fmaf(a[9],  x2.y, s2);
    s2 = fmaf(a[10], x2.z, s2); s2 = fmaf(a[11], x2.w, s2);
    s3 = fmaf(a[12], x3.x, s3); s3 = fmaf(a[13], x3.y, s3);
    s3 = fmaf(a[14], x3.z, s3); s3 = fmaf(a[15], x3.w, s3);
    float4 y0 = w4[4], y1 = w4[5], y2 = w4[6], y3 = w4[7];
    s0 = fmaf(a[16], y0.x, s0); s0 = fmaf(a[17], y0.y, s0);
    s0 = fmaf(a[18], y0.z, s0); s0 = fmaf(a[19], y0.w, s0);
    s1 = fmaf(a[20], y1.x, s1); s1 = fmaf(a[21], y1.y, s1);
    s1 = fmaf(a[22], y1.z, s1); s1 = fmaf(a[23], y1.w, s1);
    s2 = fmaf(a[24], y2.x, s2); s2 = fmaf(a[25], y2.y, s2);
    s2 = fmaf(a[26], y2.z, s2); s2 = fmaf(a[27], y2.w, s2);
    s3 = fmaf(a[28], y3.x, s3); s3 = fmaf(a[29], y3.y, s3);
    s3 = fmaf(a[30], y3.z, s3); s3 = fmaf(a[31], y3.w, s3);
    return (s0 + s1) + (s2 + s3);
}

__global__ void __launch_bounds__(THREADS, 1)
repformer_kernel(const float* __restrict__ g2,
                 const float* __restrict__ h2,
                 const float* __restrict__ sw,
                 const float* __restrict__ wqk,
                 const float* __restrict__ wv,
                 const float* __restrict__ wh,
                 const float* __restrict__ bh,
                 const float* __restrict__ weq,
                 const int*   __restrict__ mask,
                 float* __restrict__ outg,
                 float* __restrict__ outh)
{
    extern __shared__ __align__(16) char smem_raw[];
    Smem& s = *reinterpret_cast<Smem*>(smem_raw);

    const int tid  = threadIdx.x;
    const int row  = tid >> 1;     // attention row owned by this lane-pair
    const int half = tid & 1;      // k-parity handled by this lane
    const int loc  = blockIdx.x;

    const float* g2l = g2 + (size_t)loc * NNEI * NG2;
    const float* h2l = h2 + (size_t)loc * NNEI * 3;
    const float* swl = sw + (size_t)loc * NNEI;
    const int*   ml  = mask + (size_t)loc * NNEI;

    // ---- stage weights / per-loc small tensors into smem ----
    for (int i = tid; i < 32 * 256; i += THREADS) s.wqkT[i & 255][i >> 8] = wqk[i];
    for (int i = tid; i < 32 * 128; i += THREADS) s.wvT[i & 127][i >> 7] = wv[i];
    for (int i = tid; i < 128 * 32; i += THREADS) (&s.wh[0][0])[i] = wh[i];
    for (int i = tid; i < NNEI * 3; i += THREADS) s.h2s[i / 3][i % 3] = h2l[i];
    if (tid < NNEI) {
        float sv = swl[tid];
        s.sw[tid] = sv;
        s.swm[tid] = ml[tid] ? sv : 0.0f;
    }
    if (tid < 32) s.bh[tid] = bh[tid];
    if (tid < 4)  s.weq[tid] = weq[tid];
    __syncthreads();

    // ---- per-thread row state (both pair lanes hold the full row) ----
    float rg2[NG2];
    {
        const float4* gr = reinterpret_cast<const float4*>(g2l + (size_t)row * NG2);
        #pragma unroll
        for (int i = 0; i < 8; ++i) {
            float4 v = gr[i];
            rg2[4 * i + 0] = v.x; rg2[4 * i + 1] = v.y;
            rg2[4 * i + 2] = v.z; rg2[4 * i + 3] = v.w;
        }
    }
    float rh2[3] = { s.h2s[row][0], s.h2s[row][1], s.h2s[row][2] };
    const float rsw  = s.sw[row];
    const float rswm = s.swm[row];

    float g2o[NG2];
    #pragma unroll
    for (int j = 0; j < NG2; ++j) g2o[j] = half ? 0.0f : s.bh[j];
    float och0 = 0.f, och1 = 0.f, och2 = 0.f;

    float* arow = &s.A[row * 130];

    for (int h = 0; h < NH; ++h) {
        // ---- phase A: Q full per lane (regs); K/V split by half ----
        float rq[ND];
        #pragma unroll 4
        for (int d = 0; d < ND; ++d)
            rq[d] = dot32(rg2, s.wqkT[d * 8 + h]);
        #pragma unroll 4
        for (int dd = 0; dd < 16; ++dd) {
            int d = half * 16 + dd;
            s.K[row][d] = dot32(rg2, s.wqkT[d * 8 + 4 + h]);
        }
        #pragma unroll 4
        for (int gg = 0; gg < 16; ++gg) {
            int g = half * 16 + gg;
            s.V[row][g] = dot32(rg2, s.wvT[g * 4 + h]);
        }
        __syncthreads();

        // ---- phase B: logits + rowmax over own parity class ----
        float mx = -3.0e38f;
        #pragma unroll 2
        for (int i = 0; i < 64; ++i) {
            int k = 2 * i + half;
            float dot = dot32(rq, s.K[k]);
            float h20 = s.h2s[k][0], h21 = s.h2s[k][1], h22 = s.h2s[k][2];
            float h2d = fmaf(rh2[0], h20, fmaf(rh2[1], h21, rh2[2] * h22));
            float lg = fmaf(dot * INV_SQRT_D * h2d + ATTNW_SHIFT,
                            rsw * s.sw[k], -ATTNW_SHIFT);
            mx = fmaxf(mx, lg);
            arow[k] = lg;
        }
        mx = fmaxf(mx, __shfl_xor_sync(0xffffffffu, mx, 1));

        // ---- exp + sum ----
        float sm0 = 0.f, sm1 = 0.f;
        #pragma unroll 4
        for (int i = 0; i < 64; i += 2) {
            int k0 = 2 * i + half, k1 = 2 * (i + 1) + half;
            float e0 = __expf(arow[k0] - mx);
            float e1 = __expf(arow[k1] - mx);
            sm0 += e0; sm1 += e1;
            arow[k0] = e0; arow[k1] = e1;
        }
        float ssum = sm0 + sm1;
        ssum += __shfl_xor_sync(0xffffffffu, ssum, 1);
        float rowscale = rswm / (ssum * SQRT3);

        // ---- phase C: A@V (32 cols) and A@h2 (3 cols) over own parity ----
        float acc[NG2];
        #pragma unroll
        for (int g = 0; g < NG2; ++g) acc[g] = 0.f;
        float oh0 = 0.f, oh1 = 0.f, oh2 = 0.f;

        #pragma unroll 2
        for (int i = 0; i < 64; ++i) {
            int k = 2 * i + half;
            float e = arow[k];
            float h20 = s.h2s[k][0], h21 = s.h2s[k][1], h22 = s.h2s[k][2];
            float h2d = fmaf(rh2[0], h20, fmaf(rh2[1], h21, rh2[2] * h22));
            float a = e * s.swm[k] * h2d * rowscale;
            const float4* vr = reinterpret_cast<const float4*>(s.V[k]);
            #pragma unroll
            for (int g4 = 0; g4 < 8; ++g4) {
                float4 v = vr[g4];
                acc[4 * g4 + 0] = fmaf(a, v.x, acc[4 * g4 + 0]);
                acc[4 * g4 + 1] = fmaf(a, v.y, acc[4 * g4 + 1]);
                acc[4 * g4 + 2] = fmaf(a, v.z, acc[4 * g4 + 2]);
                acc[4 * g4 + 3] = fmaf(a, v.w, acc[4 * g4 + 3]);
            }
            oh0 = fmaf(a, h20, oh0);
            oh1 = fmaf(a, h21, oh1);
            oh2 = fmaf(a, h22, oh2);
        }
        // combine pair partials (both lanes end with full sums)
        #pragma unroll
        for (int g = 0; g < NG2; ++g)
            acc[g] += __shfl_xor_sync(0xffffffffu, acc[g], 1);
        oh0 += __shfl_xor_sync(0xffffffffu, oh0, 1);
        oh1 += __shfl_xor_sync(0xffffffffu, oh1, 1);
        oh2 += __shfl_xor_sync(0xffffffffu, oh2, 1);

        float weqh = s.weq[h];
        och0 = fmaf(weqh, oh0, och0);
        och1 = fmaf(weqh, oh1, och1);
        och2 = fmaf(weqh, oh2, och2);

        // ---- fold acc through w_head; each lane folds its 16 g's ----
        #pragma unroll 4
        for (int gg = 0; gg < 16; ++gg) {
            int g = half * 16 + gg;
            const float4* wr = reinterpret_cast<const float4*>(s.wh[g * 4 + h]);
            float ag = acc[g];
            #pragma unroll
            for (int j4 = 0; j4 < 8; ++j4) {
                float4 w = wr[j4];
                g2o[4 * j4 + 0] = fmaf(ag, w.x, g2o[4 * j4 + 0]);
                g2o[4 * j4 + 1] = fmaf(ag, w.y, g2o[4 * j4 + 1]);
                g2o[4 * j4 + 2] = fmaf(ag, w.z, g2o[4 * j4 + 2]);
                g2o[4 * j4 + 3] = fmaf(ag, w.w, g2o[4 * j4 + 3]);
            }
        }
        __syncthreads();   // guard K/V reuse by next head
    }

    // ---- combine pair g2o partials, write outputs (16 floats per lane) ----
    #pragma unroll
    for (int j = 0; j < NG2; ++j)
        g2o[j] += __shfl_xor_sync(0xffffffffu, g2o[j], 1);

    float* go = outg + ((size_t)loc * NNEI + row) * NG2 + half * 16;
    #pragma unroll
    for (int j4 = 0; j4 < 4; ++j4) {
        int j = half * 16 + 4 * j4;
        float4 v = make_float4(g2o[j + 0], g2o[j + 1], g2o[j + 2], g2o[j + 3]);
        reinterpret_cast<float4*>(go)[j4] = v;
    }
    if (outh && half == 0) {
        float* ho = outh + ((size_t)loc * NNEI + row) * 3;
        ho[0] = och0; ho[1] = och1; ho[2] = och2;
    }
}

extern "C" void kernel_launch(void* const* d_in, const int* in_sizes, int n_in,
                              void* d_out, int out_size) {
    const float* g2  = (const float*)d_in[0];
    const float* h2  = (const float*)d_in[1];
    const float* sw  = (const float*)d_in[2];
    const float* wqk = (const float*)d_in[3];
    const float* wv  = (const float*)d_in[4];
    const float* wh  = (const float*)d_in[5];
    const float* bh  = (const float*)d_in[6];
    const float* weq = (const float*)d_in[7];
    const int*   msk = (const int*)d_in[8];

    int nloc = in_sizes[2] / NNEI;     // sw has nloc*nnei elements
    float* outg = (float*)d_out;
    size_t gsz = (size_t)nloc * NNEI * NG2;
    float* outh = ((size_t)out_size >= gsz + (size_t)nloc * NNEI * 3)
                      ? outg + gsz : nullptr;

    cudaFuncSetAttribute(repformer_kernel,
                         cudaFuncAttributeMaxDynamicSharedMemorySize,
                         (int)sizeof(Smem));
    repformer_kernel<<<nloc, THREADS, sizeof(Smem)>>>(
        g2, h2, sw, wqk, wv, wh, bh, weq, msk, outg, outh);
}

// round 3
// speedup vs baseline: 1.0008x; 1.0008x over previous
#include <cuda_runtime.h>

#define NNEI 128
#define NG2  32
#define ND   32
#define NH   4
#define THREADS 256

#define ATTNW_SHIFT 20.0f
#define INV_SQRT_D  0.17677669529663687f   // 1/sqrt(32)
#define SQRT3       1.7320508075688772f

struct Smem {
    float wqkT[256][32];   // transposed w_qk: [j][c], j = d*8 + head_slot
    float wvT[128][32];    // transposed w_v:  [j][c], j = g*4 + h
    float wh[128][32];     // w_head natural [m][j]
    float K[128][36];      // K rows for current head (stride 36 = 4 banks)
    float V[128][36];      // V rows for current head
    float A[128 * 130];    // logits/exp rows; stride 130 (== 2 mod 32) -> conflict-free
    float h2s[128][4];
    float sw[128];
    float swm[128];        // sw * mask
    float bh[32];
    float weq[4];
};

__device__ __forceinline__ float dot32(const float* a, const float* w) {
    const float4* w4 = reinterpret_cast<const float4*>(w);
    float s0 = 0.f, s1 = 0.f, s2 = 0.f, s3 = 0.f;
    float4 x0 = w4[0], x1 = w4[1], x2 = w4[2], x3 = w4[3];
    s0 = fmaf(a[0],  x0.x, s0); s0 = fmaf(a[1],  x0.y, s0);
    s0 = fmaf(a[2],  x0.z, s0); s0 = fmaf(a[3],  x0.w, s0);
    s1 = fmaf(a[4],  x1.x, s1); s1 = fmaf(a[5],  x1.y, s1);
    s1 = fmaf(a[6],  x1.z, s1); s1 = fmaf(a[7],  x1.w, s1);
    s2 = fmaf(a[8],  x2.x, s2); s2 = fmaf(a[9],  x2.y, s2);
    s2 = fmaf(a[10], x2.z, s2); s2 = fmaf(a[11], x2.w, s2);
    s3 = fmaf(a[12], x3.x, s3); s3 = fmaf(a[13], x3.y, s3);
    s3 = fmaf(a[14], x3.z, s3); s3 = fmaf(a[15], x3.w, s3);
    float4 y0 = w4[4], y1 = w4[5], y2 = w4[6], y3 = w4[7];
    s0 = fmaf(a[16], y0.x, s0); s0 = fmaf(a[17], y0.y, s0);
    s0 = fmaf(a[18], y0.z, s0); s0 = fmaf(a[19], y0.w, s0);
    s1 = fmaf(a[20], y1.x, s1); s1 = fmaf(a[21], y1.y, s1);
    s1 = fmaf(a[22], y1.z, s1); s1 = fmaf(a[23], y1.w, s1);
    s2 = fmaf(a[24], y2.x, s2); s2 = fmaf(a[25], y2.y, s2);
    s2 = fmaf(a[26], y2.z, s2); s2 = fmaf(a[27], y2.w, s2);
    s3 = fmaf(a[28], y3.x, s3); s3 = fmaf(a[29], y3.y, s3);
    s3 = fmaf(a[30], y3.z, s3); s3 = fmaf(a[31], y3.w, s3);
    return (s0 + s1) + (s2 + s3);
}

__global__ void __launch_bounds__(THREADS, 1)
repformer_kernel(const float* __restrict__ g2,
                 const float* __restrict__ h2,
                 const float* __restrict__ sw,
                 const float* __restrict__ wqk,
                 const float* __restrict__ wv,
                 const float* __restrict__ wh,
                 const float* __restrict__ bh,
                 const float* __restrict__ weq,
                 const int*   __restrict__ mask,
                 float* __restrict__ outg,
                 float* __restrict__ outh)
{
    extern __shared__ __align__(16) char smem_raw[];
    Smem& s = *reinterpret_cast<Smem*>(smem_raw);

    const int tid  = threadIdx.x;
    const int row  = tid >> 1;     // attention row owned by this lane-pair
    const int half = tid & 1;      // k-parity handled by this lane
    const int loc  = blockIdx.x;

    const float* g2l = g2 + (size_t)loc * NNEI * NG2;
    const float* h2l = h2 + (size_t)loc * NNEI * 3;
    const float* swl = sw + (size_t)loc * NNEI;
    const int*   ml  = mask + (size_t)loc * NNEI;

    // ---- stage weights / per-loc small tensors into smem ----
    for (int i = tid; i < 32 * 256; i += THREADS) s.wqkT[i & 255][i >> 8] = wqk[i];
    for (int i = tid; i < 32 * 128; i += THREADS) s.wvT[i & 127][i >> 7] = wv[i];
    for (int i = tid; i < 128 * 32; i += THREADS) (&s.wh[0][0])[i] = wh[i];
    for (int i = tid; i < NNEI * 3; i += THREADS) s.h2s[i / 3][i % 3] = h2l[i];
    if (tid < NNEI) {
        float sv = swl[tid];
        s.sw[tid] = sv;
        s.swm[tid] = ml[tid] ? sv : 0.0f;
    }
    if (tid < 32) s.bh[tid] = bh[tid];
    if (tid < 4)  s.weq[tid] = weq[tid];
    __syncthreads();

    // ---- per-thread row state (both pair lanes hold the full row) ----
    float rg2[NG2];
    {
        const float4* gr = reinterpret_cast<const float4*>(g2l + (size_t)row * NG2);
        #pragma unroll
        for (int i = 0; i < 8; ++i) {
            float4 v = gr[i];
            rg2[4 * i + 0] = v.x; rg2[4 * i + 1] = v.y;
            rg2[4 * i + 2] = v.z; rg2[4 * i + 3] = v.w;
        }
    }
    float rh2[3] = { s.h2s[row][0], s.h2s[row][1], s.h2s[row][2] };
    const float rsw  = s.sw[row];
    const float rswm = s.swm[row];

    float g2o[NG2];
    #pragma unroll
    for (int j = 0; j < NG2; ++j) g2o[j] = half ? 0.0f : s.bh[j];
    float och0 = 0.f, och1 = 0.f, och2 = 0.f;

    float* arow = &s.A[row * 130];

    for (int h = 0; h < NH; ++h) {
        // ---- phase A: Q full per lane (regs); K/V split by half ----
        float rq[ND];
        #pragma unroll 4
        for (int d = 0; d < ND; ++d)
            rq[d] = dot32(rg2, s.wqkT[d * 8 + h]);
        #pragma unroll 4
        for (int dd = 0; dd < 16; ++dd) {
            int d = half * 16 + dd;
            s.K[row][d] = dot32(rg2, s.wqkT[d * 8 + 4 + h]);
        }
        #pragma unroll 4
        for (int gg = 0; gg < 16; ++gg) {
            int g = half * 16 + gg;
            s.V[row][g] = dot32(rg2, s.wvT[g * 4 + h]);
        }
        __syncthreads();

        // ---- phase B: logits + rowmax over own parity class ----
        float mx = -3.0e38f;
        #pragma unroll 2
        for (int i = 0; i < 64; ++i) {
            int k = 2 * i + half;
            float dot = dot32(rq, s.K[k]);
            float h20 = s.h2s[k][0], h21 = s.h2s[k][1], h22 = s.h2s[k][2];
            float h2d = fmaf(rh2[0], h20, fmaf(rh2[1], h21, rh2[2] * h22));
            float lg = fmaf(dot * INV_SQRT_D * h2d + ATTNW_SHIFT,
                            rsw * s.sw[k], -ATTNW_SHIFT);
            mx = fmaxf(mx, lg);
            arow[k] = lg;
        }
        mx = fmaxf(mx, __shfl_xor_sync(0xffffffffu, mx, 1));

        // ---- exp + sum ----
        float sm0 = 0.f, sm1 = 0.f;
        #pragma unroll 4
        for (int i = 0; i < 64; i += 2) {
            int k0 = 2 * i + half, k1 = 2 * (i + 1) + half;
            float e0 = __expf(arow[k0] - mx);
            float e1 = __expf(arow[k1] - mx);
            sm0 += e0; sm1 += e1;
            arow[k0] = e0; arow[k1] = e1;
        }
        float ssum = sm0 + sm1;
        ssum += __shfl_xor_sync(0xffffffffu, ssum, 1);
        float rowscale = rswm / (ssum * SQRT3);

        // ---- phase C: A@V (32 cols) and A@h2 (3 cols) over own parity ----
        float acc[NG2];
        #pragma unroll
        for (int g = 0; g < NG2; ++g) acc[g] = 0.f;
        float oh0 = 0.f, oh1 = 0.f, oh2 = 0.f;

        #pragma unroll 2
        for (int i = 0; i < 64; ++i) {
            int k = 2 * i + half;
            float e = arow[k];
            float h20 = s.h2s[k][0], h21 = s.h2s[k][1], h22 = s.h2s[k][2];
            float h2d = fmaf(rh2[0], h20, fmaf(rh2[1], h21, rh2[2] * h22));
            float a = e * s.swm[k] * h2d * rowscale;
            const float4* vr = reinterpret_cast<const float4*>(s.V[k]);
            #pragma unroll
            for (int g4 = 0; g4 < 8; ++g4) {
                float4 v = vr[g4];
                acc[4 * g4 + 0] = fmaf(a, v.x, acc[4 * g4 + 0]);
                acc[4 * g4 + 1] = fmaf(a, v.y, acc[4 * g4 + 1]);
                acc[4 * g4 + 2] = fmaf(a, v.z, acc[4 * g4 + 2]);
                acc[4 * g4 + 3] = fmaf(a, v.w, acc[4 * g4 + 3]);
            }
            oh0 = fmaf(a, h20, oh0);
            oh1 = fmaf(a, h21, oh1);
            oh2 = fmaf(a, h22, oh2);
        }
        // combine pair partials (both lanes end with full sums)
        #pragma unroll
        for (int g = 0; g < NG2; ++g)
            acc[g] += __shfl_xor_sync(0xffffffffu, acc[g], 1);
        oh0 += __shfl_xor_sync(0xffffffffu, oh0, 1);
        oh1 += __shfl_xor_sync(0xffffffffu, oh1, 1);
        oh2 += __shfl_xor_sync(0xffffffffu, oh2, 1);

        float weqh = s.weq[h];
        och0 = fmaf(weqh, oh0, och0);
        och1 = fmaf(weqh, oh1, och1);
        och2 = fmaf(weqh, oh2, och2);

        // ---- fold acc through w_head; each lane folds its 16 g's ----
        #pragma unroll 4
        for (int gg = 0; gg < 16; ++gg) {
            int g = half * 16 + gg;
            const float4* wr = reinterpret_cast<const float4*>(s.wh[g * 4 + h]);
            float ag = acc[g];
            #pragma unroll
            for (int j4 = 0; j4 < 8; ++j4) {
                float4 w = wr[j4];
                g2o[4 * j4 + 0] = fmaf(ag, w.x, g2o[4 * j4 + 0]);
                g2o[4 * j4 + 1] = fmaf(ag, w.y, g2o[4 * j4 + 1]);
                g2o[4 * j4 + 2] = fmaf(ag, w.z, g2o[4 * j4 + 2]);
                g2o[4 * j4 + 3] = fmaf(ag, w.w, g2o[4 * j4 + 3]);
            }
        }
        __syncthreads();   // guard K/V reuse by next head
    }

    // ---- combine pair g2o partials, write outputs (16 floats per lane) ----
    #pragma unroll
    for (int j = 0; j < NG2; ++j)
        g2o[j] += __shfl_xor_sync(0xffffffffu, g2o[j], 1);

    float* go = outg + ((size_t)loc * NNEI + row) * NG2 + half * 16;
    #pragma unroll
    for (int j4 = 0; j4 < 4; ++j4) {
        int j = half * 16 + 4 * j4;
        float4 v = make_float4(g2o[j + 0], g2o[j + 1], g2o[j + 2], g2o[j + 3]);
        reinterpret_cast<float4*>(go)[j4] = v;
    }
    if (outh && half == 0) {
        float* ho = outh + ((size_t)loc * NNEI + row) * 3;
        ho[0] = och0; ho[1] = och1; ho[2] = och2;
    }
}

extern "C" void kernel_launch(void* const* d_in, const int* in_sizes, int n_in,
                              void* d_out, int out_size) {
    const float* g2  = (const float*)d_in[0];
    const float* h2  = (const float*)d_in[1];
    const float* sw  = (const float*)d_in[2];
    const float* wqk = (const float*)d_in[3];
    const float* wv  = (const float*)d_in[4];
    const float* wh  = (const float*)d_in[5];
    const float* bh  = (const float*)d_in[6];
    const float* weq = (const float*)d_in[7];
    const int*   msk = (const int*)d_in[8];

    int nloc = in_sizes[2] / NNEI;     // sw has nloc*nnei elements
    float* outg = (float*)d_out;
    size_t gsz = (size_t)nloc * NNEI * NG2;
    float* outh = ((size_t)out_size >= gsz + (size_t)nloc * NNEI * 3)
                      ? outg + gsz : nullptr;

    cudaFuncSetAttribute(repformer_kernel,
                         cudaFuncAttributeMaxDynamicSharedMemorySize,
                         (int)sizeof(Smem));
    repformer_kernel<<<nloc, THREADS, sizeof(Smem)>>>(
        g2, h2, sw, wqk, wv, wh, bh, weq, msk, outg, outh);
}

// round 6
// speedup vs baseline: 1.3766x; 1.3755x over previous
#include <cuda_runtime.h>
#include <cstdint>

#define THREADS 128
#define ATTNW_SHIFT 20.0f
#define INV_SQRT_D  0.17677669529663687f
#define SQRT3       1.7320508075688772f

// smem float-index layout (all strides == 4 mod 32 -> conflict-free frags)
#define SA 36
#define SW 388
#define SP 100
#define SQ 132
#define F_G2   0        // 128*36  = 4608
#define F_WALL 4608     // 32*388  = 12416
#define F_PH   17024    // 128*100 = 12800
#define F_APR  29824    // 128*132 = 16896 (also init scratch)
#define F_H2SW 46720    // 128 float4
#define F_SWM  47232    // 128
#define F_BH   47360    // 32
#define F_WEQ  47392    // 4
#define SMEM_BYTES 189696

static __device__ __forceinline__ void hilo(float v, uint32_t& h, uint32_t& l) {
    asm("cvt.rna.tf32.f32 %0, %1;" : "=r"(h) : "f"(v));
    float r = v - __uint_as_float(h);
    asm("cvt.rna.tf32.f32 %0, %1;" : "=r"(l) : "f"(r));
}
static __device__ __forceinline__ void mma8(float* d, const uint32_t* a,
                                            uint32_t b0, uint32_t b1) {
    asm volatile("mma.sync.aligned.m16n8k8.row.col.f32.tf32.tf32.f32 "
                 "{%0,%1,%2,%3}, {%4,%5,%6,%7}, {%8,%9}, {%0,%1,%2,%3};"
                 : "+f"(d[0]), "+f"(d[1]), "+f"(d[2]), "+f"(d[3])
                 : "r"(a[0]), "r"(a[1]), "r"(a[2]), "r"(a[3]), "r"(b0), "r"(b1));
}
// A-frag (f32 smem, stride S): base points at row (m0+mt*16+g), element k0+t
static __device__ __forceinline__ void ldA(const float* base, int S, int k,
                                           uint32_t* hi, uint32_t* lo) {
    float f0 = base[k], f1 = base[8 * S + k], f2 = base[k + 4], f3 = base[8 * S + k + 4];
    hilo(f0, hi[0], lo[0]); hilo(f1, hi[1], lo[1]);
    hilo(f2, hi[2], lo[2]); hilo(f3, hi[3], lo[3]);
}

__global__ void __launch_bounds__(THREADS, 1)
rep_mma_kernel(const float* __restrict__ g2, const float* __restrict__ h2,
               const float* __restrict__ sw, const float* __restrict__ wqk,
               const float* __restrict__ wv, const float* __restrict__ wh,
               const float* __restrict__ bh, const float* __restrict__ weq,
               const int* __restrict__ mask, float* __restrict__ outg,
               float* __restrict__ outh)
{
    extern __shared__ __align__(16) float smf[];
    const int tid = threadIdx.x, w = tid >> 5, lane = tid & 31;
    const int g = lane >> 2, t = lane & 3;
    const int m0 = w * 32;
    const int loc = blockIdx.x;

    const float* g2l = g2 + (size_t)loc * 128 * 32;
    const float* h2l = h2 + (size_t)loc * 128 * 3;
    const float* swl = sw + (size_t)loc * 128;
    const int*   ml  = mask + (size_t)loc * 128;

    // ---- stage scratch: wqk(8192) wv(4096) wh(4096) into APR region ----
    {
        const float4* s1 = (const float4*)wqk;
        float4* d1 = (float4*)(smf + F_APR);
        #pragma unroll
        for (int i = 0; i < 16; ++i) d1[tid + i * 128] = s1[tid + i * 128];
        const float4* s2 = (const float4*)wv;
        float4* d2 = (float4*)(smf + F_APR + 8192);
        #pragma unroll
        for (int i = 0; i < 8; ++i) d2[tid + i * 128] = s2[tid + i * 128];
        const float4* s3 = (const float4*)wh;
        float4* d3 = (float4*)(smf + F_APR + 12288);
        #pragma unroll
        for (int i = 0; i < 8; ++i) d3[tid + i * 128] = s3[tid + i * 128];
    }
    // g2 rows (thread = row)
    {
        const float4* gr = (const float4*)(g2l + (size_t)tid * 32);
        float4* dst = (float4*)(smf + F_G2 + tid * SA);
        #pragma unroll
        for (int i = 0; i < 8; ++i) dst[i] = gr[i];
    }
    {
        float a = h2l[tid * 3], b = h2l[tid * 3 + 1], c = h2l[tid * 3 + 2];
        float sv = swl[tid];
        ((float4*)(smf + F_H2SW))[tid] = make_float4(a, b, c, sv);
        smf[F_SWM + tid] = ml[tid] ? sv : 0.0f;
    }
    if (tid < 32) smf[F_BH + tid] = bh[tid];
    if (tid < 4)  smf[F_WEQ + tid] = weq[tid];
    __syncthreads();

    // ---- build Wall[k=32][384]: per head h: cols h*96+{0..31 Q, 32..63 K, 64..95 C} ----
    for (int i = tid; i < 8192; i += THREADS) {
        int c = i >> 8, j = i & 255;
        int hh = j >> 6, r = j & 63;
        int src = (r < 32) ? r * 8 + hh : (r - 32) * 8 + 4 + hh;
        smf[F_WALL + c * SW + hh * 96 + r] = smf[F_APR + c * 256 + src];
    }
    {
        int hh = tid >> 5, m = tid & 31;
        float whcol[32];
        #pragma unroll 8
        for (int gg = 0; gg < 32; ++gg)
            whcol[gg] = smf[F_APR + 12288 + (gg * 4 + hh) * 32 + m];
        #pragma unroll 1
        for (int c = 0; c < 32; ++c) {
            const float* wvr = smf + F_APR + 8192 + c * 128 + hh;
            float acc = 0.f;
            #pragma unroll
            for (int gg = 0; gg < 32; ++gg) acc = fmaf(wvr[gg * 4], whcol[gg], acc);
            smf[F_WALL + c * SW + hh * 96 + 64 + m] = acc;
        }
    }
    __syncthreads();

    // ---- persistent per-thread state ----
    float oacc[2][4][4];
    #pragma unroll
    for (int a = 0; a < 2; ++a)
        #pragma unroll
        for (int b = 0; b < 4; ++b)
            #pragma unroll
            for (int c = 0; c < 4; ++c) oacc[a][b][c] = 0.f;
    float och[4][3] = {};
    float4 rH[4]; float rswm[4];
    #pragma unroll
    for (int mt2 = 0; mt2 < 4; ++mt2) {
        int row = m0 + (mt2 >> 1) * 16 + g + (mt2 & 1) * 8;
        rH[mt2] = ((float4*)(smf + F_H2SW))[row];
        rswm[mt2] = smf[F_SWM + row];
    }

    #pragma unroll 1
    for (int h = 0; h < 4; ++h) {
        // ======== GEMM_P: Ph[m][0..95] = g2 @ [Wq|Wk|Wc]_h ========
        #pragma unroll 1
        for (int chunk = 0; chunk < 2; ++chunk) {
            float pacc[2][6][4];
            #pragma unroll
            for (int a = 0; a < 2; ++a)
                #pragma unroll
                for (int b = 0; b < 6; ++b)
                    #pragma unroll
                    for (int c = 0; c < 4; ++c) pacc[a][b][c] = 0.f;
            #pragma unroll 1
            for (int kk = 0; kk < 4; ++kk) {
                int k0 = kk * 8;
                uint32_t ahi[2][4], alo[2][4];
                #pragma unroll
                for (int mt = 0; mt < 2; ++mt)
                    ldA(smf + F_G2 + (m0 + mt * 16 + g) * SA, SA, k0 + t, ahi[mt], alo[mt]);
                #pragma unroll
                for (int nt = 0; nt < 6; ++nt) {
                    int col = h * 96 + chunk * 48 + nt * 8 + g;
                    float b0f = smf[F_WALL + (k0 + t) * SW + col];
                    float b1f = smf[F_WALL + (k0 + t + 4) * SW + col];
                    uint32_t bh0, bl0, bh1, bl1;
                    hilo(b0f, bh0, bl0); hilo(b1f, bh1, bl1);
                    #pragma unroll
                    for (int mt = 0; mt < 2; ++mt) {
                        mma8(pacc[mt][nt], ahi[mt], bh0, bh1);
                        mma8(pacc[mt][nt], alo[mt], bh0, bh1);
                        mma8(pacc[mt][nt], ahi[mt], bl0, bl1);
                    }
                }
            }
            #pragma unroll
            for (int mt = 0; mt < 2; ++mt)
                #pragma unroll
                for (int nt = 0; nt < 6; ++nt)
                    #pragma unroll
                    for (int hb = 0; hb < 2; ++hb) {
                        int row = m0 + mt * 16 + g + hb * 8;
                        int col = chunk * 48 + nt * 8 + 2 * t;
                        *(float2*)(smf + F_PH + row * SP + col) =
                            make_float2(pacc[mt][nt][hb * 2], pacc[mt][nt][hb * 2 + 1]);
                    }
        }
        __syncthreads();

        // ======== GEMM_S: sacc = Q @ K^T (in regs) ========
        float sacc[2][16][4];
        #pragma unroll
        for (int a = 0; a < 2; ++a)
            #pragma unroll
            for (int b = 0; b < 16; ++b)
                #pragma unroll
                for (int c = 0; c < 4; ++c) sacc[a][b][c] = 0.f;
        #pragma unroll 1
        for (int kk = 0; kk < 4; ++kk) {
            int k0 = kk * 8;
            uint32_t ahi[2][4], alo[2][4];
            #pragma unroll
            for (int mt = 0; mt < 2; ++mt)
                ldA(smf + F_PH + (m0 + mt * 16 + g) * SP, SP, k0 + t, ahi[mt], alo[mt]);
            #pragma unroll
            for (int nt = 0; nt < 16; ++nt) {
                float b0f = smf[F_PH + (nt * 8 + g) * SP + 32 + k0 + t];
                float b1f = smf[F_PH + (nt * 8 + g) * SP + 32 + k0 + t + 4];
                uint32_t bh0, bl0, bh1, bl1;
                hilo(b0f, bh0, bl0); hilo(b1f, bh1, bl1);
                #pragma unroll
                for (int mt = 0; mt < 2; ++mt) {
                    mma8(sacc[mt][nt], ahi[mt], bh0, bh1);
                    mma8(sacc[mt][nt], alo[mt], bh0, bh1);
                    mma8(sacc[mt][nt], ahi[mt], bl0, bl1);
                }
            }
        }

        // ======== softmax in registers ========
        float mx[4] = {-3.0e38f, -3.0e38f, -3.0e38f, -3.0e38f};
        #pragma unroll
        for (int nt = 0; nt < 16; ++nt)
            #pragma unroll
            for (int b = 0; b < 2; ++b) {
                int col = nt * 8 + 2 * t + b;
                float4 hc = ((float4*)(smf + F_H2SW))[col];
                #pragma unroll
                for (int mt2 = 0; mt2 < 4; ++mt2) {
                    float v = sacc[mt2 >> 1][nt][(mt2 & 1) * 2 + b];
                    float h2d = fmaf(rH[mt2].x, hc.x, fmaf(rH[mt2].y, hc.y, rH[mt2].z * hc.z));
                    float lg = fmaf(v * INV_SQRT_D * h2d + ATTNW_SHIFT,
                                    rH[mt2].w * hc.w, -ATTNW_SHIFT);
                    sacc[mt2 >> 1][nt][(mt2 & 1) * 2 + b] = lg;
                    mx[mt2] = fmaxf(mx[mt2], lg);
                }
            }
        #pragma unroll
        for (int mt2 = 0; mt2 < 4; ++mt2) {
            mx[mt2] = fmaxf(mx[mt2], __shfl_xor_sync(0xffffffffu, mx[mt2], 1));
            mx[mt2] = fmaxf(mx[mt2], __shfl_xor_sync(0xffffffffu, mx[mt2], 2));
        }
        float ssum[4] = {}, ochp[4][3] = {};
        #pragma unroll
        for (int nt = 0; nt < 16; ++nt)
            #pragma unroll
            for (int b = 0; b < 2; ++b) {
                int col = nt * 8 + 2 * t + b;
                float4 hc = ((float4*)(smf + F_H2SW))[col];
                float smc = smf[F_SWM + col];
                #pragma unroll
                for (int mt2 = 0; mt2 < 4; ++mt2) {
                    float lg = sacc[mt2 >> 1][nt][(mt2 & 1) * 2 + b];
                    float e = __expf(lg - mx[mt2]);
                    ssum[mt2] += e;
                    float h2d = fmaf(rH[mt2].x, hc.x, fmaf(rH[mt2].y, hc.y, rH[mt2].z * hc.z));
                    float ap = e * smc * h2d;
                    sacc[mt2 >> 1][nt][(mt2 & 1) * 2 + b] = ap;
                    ochp[mt2][0] = fmaf(ap, hc.x, ochp[mt2][0]);
                    ochp[mt2][1] = fmaf(ap, hc.y, ochp[mt2][1]);
                    ochp[mt2][2] = fmaf(ap, hc.z, ochp[mt2][2]);
                }
            }
        float rowscale[4];
        float wqh = smf[F_WEQ + h];
        #pragma unroll
        for (int mt2 = 0; mt2 < 4; ++mt2) {
            float s = ssum[mt2];
            s += __shfl_xor_sync(0xffffffffu, s, 1);
            s += __shfl_xor_sync(0xffffffffu, s, 2);
            rowscale[mt2] = rswm[mt2] / (s * SQRT3);
            float f = wqh * rowscale[mt2];
            och[mt2][0] = fmaf(f, ochp[mt2][0], och[mt2][0]);
            och[mt2][1] = fmaf(f, ochp[mt2][1], och[mt2][1]);
            och[mt2][2] = fmaf(f, ochp[mt2][2], och[mt2][2]);
        }
        // A' -> smem (warp-private rows, no sync needed)
        #pragma unroll
        for (int nt = 0; nt < 16; ++nt)
            #pragma unroll
            for (int mt2 = 0; mt2 < 4; ++mt2) {
                int row = m0 + (mt2 >> 1) * 16 + g + (mt2 & 1) * 8;
                float a0 = sacc[mt2 >> 1][nt][(mt2 & 1) * 2] * rowscale[mt2];
                float a1 = sacc[mt2 >> 1][nt][(mt2 & 1) * 2 + 1] * rowscale[mt2];
                *(float2*)(smf + F_APR + row * SQ + nt * 8 + 2 * t) = make_float2(a0, a1);
            }

        // ======== GEMM_O: oacc += A' @ C_h ========
        #pragma unroll 1
        for (int kk = 0; kk < 16; ++kk) {
            int k0 = kk * 8;
            uint32_t ahi[2][4], alo[2][4];
            #pragma unroll
            for (int mt = 0; mt < 2; ++mt)
                ldA(smf + F_APR + (m0 + mt * 16 + g) * SQ, SQ, k0 + t, ahi[mt], alo[mt]);
            #pragma unroll
            for (int nt = 0; nt < 4; ++nt) {
                float b0f = smf[F_PH + (k0 + t) * SP + 64 + nt * 8 + g];
                float b1f = smf[F_PH + (k0 + t + 4) * SP + 64 + nt * 8 + g];
                uint32_t bh0, bl0, bh1, bl1;
                hilo(b0f, bh0, bl0); hilo(b1f, bh1, bl1);
                #pragma unroll
                for (int mt = 0; mt < 2; ++mt) {
                    mma8(oacc[mt][nt], ahi[mt], bh0, bh1);
                    mma8(oacc[mt][nt], alo[mt], bh0, bh1);
                    mma8(oacc[mt][nt], ahi[mt], bl0, bl1);
                }
            }
        }
        __syncthreads();   // Ph reused next head
    }

    // ---- outputs ----
    #pragma unroll
    for (int mt = 0; mt < 2; ++mt)
        #pragma unroll
        for (int hb = 0; hb < 2; ++hb) {
            int row = m0 + mt * 16 + g + hb * 8;
            float* go = outg + ((size_t)loc * 128 + row) * 32;
            #pragma unroll
            for (int nt = 0; nt < 4; ++nt) {
                int col = nt * 8 + 2 * t;
                float2 v = make_float2(oacc[mt][nt][hb * 2] + smf[F_BH + col],
                                       oacc[mt][nt][hb * 2 + 1] + smf[F_BH + col + 1]);
                *(float2*)(go + col) = v;
            }
        }
    if (outh) {
        #pragma unroll
        for (int mt2 = 0; mt2 < 4; ++mt2) {
            #pragma unroll
            for (int c = 0; c < 3; ++c) {
                och[mt2][c] += __shfl_xor_sync(0xffffffffu, och[mt2][c], 1);
                och[mt2][c] += __shfl_xor_sync(0xffffffffu, och[mt2][c], 2);
            }
            if (t == 0) {
                int row = m0 + (mt2 >> 1) * 16 + g + (mt2 & 1) * 8;
                float* ho = outh + ((size_t)loc * 128 + row) * 3;
                ho[0] = och[mt2][0]; ho[1] = och[mt2][1]; ho[2] = och[mt2][2];
            }
        }
    }
}

extern "C" void kernel_launch(void* const* d_in, const int* in_sizes, int n_in,
                              void* d_out, int out_size) {
    const float* g2  = (const float*)d_in[0];
    const float* h2  = (const float*)d_in[1];
    const float* sw  = (const float*)d_in[2];
    const float* wqk = (const float*)d_in[3];
    const float* wv  = (const float*)d_in[4];
    const float* wh  = (const float*)d_in[5];
    const float* bh  = (const float*)d_in[6];
    const float* weq = (const float*)d_in[7];
    const int*   msk = (const int*)d_in[8];

    int nloc = in_sizes[2] / 128;
    float* outg = (float*)d_out;
    size_t gsz = (size_t)nloc * 128 * 32;
    float* outh = ((size_t)out_size >= gsz + (size_t)nloc * 128 * 3) ? outg + gsz : nullptr;

    cudaFuncSetAttribute(rep_mma_kernel, cudaFuncAttributeMaxDynamicSharedMemorySize, SMEM_BYTES);
    rep_mma_kernel<<<nloc, THREADS, SMEM_BYTES>>>(g2, h2, sw, wqk, wv, wh, bh, weq, msk, outg, outh);
}

// round 10
// speedup vs baseline: 3.1387x; 2.2800x over previous
#include <cuda_runtime.h>
#include <cuda_bf16.h>
#include <cstdint>

#define THREADS 256
#define ATTNW_SHIFT 20.0f
#define INV_SQRT_D  0.17677669529663687f
#define SQRT3       1.7320508075688772f

// word(=float)-index smem layout. bf16 arrays accessed as u32 words (2 elems).
// strides (bf16 elems): G2 40, WallT 40, Ph 72, Ct 136, APR 136
// half-strides (words): 20, 20, 36, 68, 68  (all == 4 mod 8 -> conflict-free frags)
#define WG2H  0        // 128*20 = 2560
#define WG2L  2560
#define WWTH  5120     // 384*20 = 7680
#define WWTL  12800
#define WPHH  20480    // 128*36 = 4608
#define WPHL  25088
#define WCTH  29696    // 32*68 = 2176
#define WCTL  31872
#define WAPH  34048    // 128*68 = 8704
#define WAPL  42752
#define F_H2SW 51456   // 128 float4 = 512
#define F_SWM  51968   // 128
#define F_BH   52096   // 32
#define F_WEQ  52128   // 4
#define SMEM_BYTES 208640
// init-only raw-weight scratch overlays APR region:
#define F_RQK  34048   // 8192 floats
#define F_RWV  42240   // 4096
#define F_RWH  46336   // 4096

static __device__ __forceinline__ uint32_t packb(float e0, float e1) {
    uint32_t r;
    asm("cvt.rn.bf16x2.f32 %0, %1, %2;" : "=r"(r) : "f"(e1), "f"(e0));
    return r;  // low half = e0, high = e1
}
static __device__ __forceinline__ float bhi(float v) {
    return __bfloat162float(__float2bfloat16_rn(v));
}
static __device__ __forceinline__ void pack_hl(float v0, float v1,
                                               uint32_t& h, uint32_t& l) {
    h = packb(v0, v1);
    l = packb(v0 - bhi(v0), v1 - bhi(v1));
}
static __device__ __forceinline__ void mma16(float* d, uint32_t a0, uint32_t a1,
                                             uint32_t a2, uint32_t a3,
                                             uint32_t b0, uint32_t b1) {
    asm volatile("mma.sync.aligned.m16n8k16.row.col.f32.bf16.bf16.f32 "
                 "{%0,%1,%2,%3}, {%4,%5,%6,%7}, {%8,%9}, {%0,%1,%2,%3};"
                 : "+f"(d[0]), "+f"(d[1]), "+f"(d[2]), "+f"(d[3])
                 : "r"(a0), "r"(a1), "r"(a2), "r"(a3), "r"(b0), "r"(b1));
}
static __device__ __forceinline__ void mma3(float* d, const uint32_t* ah,
                                            const uint32_t* al,
                                            uint32_t bh0, uint32_t bh1,
                                            uint32_t bl0, uint32_t bl1) {
    mma16(d, ah[0], ah[1], ah[2], ah[3], bh0, bh1);
    mma16(d, al[0], al[1], al[2], al[3], bh0, bh1);
    mma16(d, ah[0], ah[1], ah[2], ah[3], bl0, bl1);
}

__global__ void __launch_bounds__(THREADS, 1)
rep_bf16_kernel(const float* __restrict__ g2, const float* __restrict__ h2,
                const float* __restrict__ sw, const float* __restrict__ wqk,
                const float* __restrict__ wv, const float* __restrict__ wh,
                const float* __restrict__ bh, const float* __restrict__ weq,
                const int* __restrict__ mask, float* __restrict__ outg,
                float* __restrict__ outh)
{
    extern __shared__ __align__(16) float smf[];
    uint32_t* smu = (uint32_t*)smf;
    const int tid = threadIdx.x, w = tid >> 5, lane = tid & 31;
    const int g = lane >> 2, t = lane & 3;
    const int m0 = w * 16;
    const int loc = blockIdx.x;

    const float* g2l = g2 + (size_t)loc * 128 * 32;
    const float* h2l = h2 + (size_t)loc * 128 * 3;
    const float* swl = sw + (size_t)loc * 128;
    const int*   ml  = mask + (size_t)loc * 128;

    // ---- stage raw weights ----
    {
        const float4* s1 = (const float4*)wqk;
        float4* d1 = (float4*)(smf + F_RQK);
        #pragma unroll
        for (int i = 0; i < 8; ++i) d1[tid + i * 256] = s1[tid + i * 256];
        const float4* s2 = (const float4*)wv;
        float4* d2 = (float4*)(smf + F_RWV);
        #pragma unroll
        for (int i = 0; i < 4; ++i) d2[tid + i * 256] = s2[tid + i * 256];
        const float4* s3 = (const float4*)wh;
        float4* d3 = (float4*)(smf + F_RWH);
        #pragma unroll
        for (int i = 0; i < 4; ++i) d3[tid + i * 256] = s3[tid + i * 256];
    }
    // ---- g2 -> bf16 hi/lo (thread = half row) ----
    {
        int r = tid >> 1, hf = tid & 1;
        const float* src = g2l + (size_t)r * 32 + hf * 16;
        float e[16];
        #pragma unroll
        for (int i = 0; i < 4; ++i) {
            float4 v = ((const float4*)src)[i];
            e[4*i] = v.x; e[4*i+1] = v.y; e[4*i+2] = v.z; e[4*i+3] = v.w;
        }
        #pragma unroll
        for (int j = 0; j < 8; ++j) {
            uint32_t hu, lu;
            pack_hl(e[2*j], e[2*j+1], hu, lu);
            smu[WG2H + r * 20 + hf * 8 + j] = hu;
            smu[WG2L + r * 20 + hf * 8 + j] = lu;
        }
    }
    if (tid < 128) {
        float a = h2l[tid * 3], b = h2l[tid * 3 + 1], c = h2l[tid * 3 + 2];
        float sv = swl[tid];
        ((float4*)(smf + F_H2SW))[tid] = make_float4(a, b, c, sv);
        smf[F_SWM + tid] = ml[tid] ? sv : 0.0f;
    }
    if (tid < 32) smf[F_BH + tid] = bh[tid];
    if (tid < 4)  smf[F_WEQ + tid] = weq[tid];
    __syncthreads();

    // ---- WallT Q/K rows: c = h*96 + r (r<64), k contiguous ----
    #pragma unroll 4
    for (int i = tid; i < 4096; i += THREADS) {
        int rqk = i >> 4, j = i & 15;
        int hh = rqk >> 6, r = rqk & 63;
        int c = hh * 96 + r;
        int src = (r < 32) ? r * 8 + hh : (r - 32) * 8 + 4 + hh;
        float v0 = smf[F_RQK + (2 * j) * 256 + src];
        float v1 = smf[F_RQK + (2 * j + 1) * 256 + src];
        uint32_t hu, lu;
        pack_hl(v0, v1, hu, lu);
        smu[WWTH + c * 20 + j] = hu;
        smu[WWTL + c * 20 + j] = lu;
    }
    // ---- WallT C rows: c = h*96 + 64 + m;  wc[k][m] = sum_g wv[k][g*4+h]*wh[g*4+h][m]
    if (tid < 128) {
        int hh = tid >> 5, m = tid & 31;
        float whcol[32];
        #pragma unroll 8
        for (int gg = 0; gg < 32; ++gg)
            whcol[gg] = smf[F_RWH + (gg * 4 + hh) * 32 + m];
        float acc[32];
        #pragma unroll 1
        for (int k = 0; k < 32; ++k) {
            const float* wvr = smf + F_RWV + k * 128 + hh;
            float s = 0.f;
            #pragma unroll
            for (int gg = 0; gg < 32; ++gg) s = fmaf(wvr[gg * 4], whcol[gg], s);
            acc[k] = s;
        }
        int c = hh * 96 + 64 + m;
        #pragma unroll
        for (int j = 0; j < 16; ++j) {
            uint32_t hu, lu;
            pack_hl(acc[2 * j], acc[2 * j + 1], hu, lu);
            smu[WWTH + c * 20 + j] = hu;
            smu[WWTL + c * 20 + j] = lu;
        }
    }
    __syncthreads();

    // ---- persistent state ----
    float oacc[4][4];
    #pragma unroll
    for (int a = 0; a < 4; ++a)
        #pragma unroll
        for (int b = 0; b < 4; ++b) oacc[a][b] = 0.f;
    float och[2][3] = {};
    float4 rH[2]; float rswm[2];
    #pragma unroll
    for (int mt2 = 0; mt2 < 2; ++mt2) {
        int row = m0 + g + mt2 * 8;
        rH[mt2] = ((float4*)(smf + F_H2SW))[row];
        rswm[mt2] = smf[F_SWM + row];
    }

    #pragma unroll 1
    for (int h = 0; h < 4; ++h) {
        // ======== GEMM_P: rows m0..m0+15, cols h*96..+95 ========
        float pacc[12][4];
        #pragma unroll
        for (int a = 0; a < 12; ++a)
            #pragma unroll
            for (int b = 0; b < 4; ++b) pacc[a][b] = 0.f;
        #pragma unroll
        for (int kk = 0; kk < 2; ++kk) {
            int wa = (m0 + g) * 20 + kk * 8 + t;
            int wb = (m0 + g + 8) * 20 + kk * 8 + t;
            uint32_t ah[4] = { smu[WG2H + wa], smu[WG2H + wb],
                               smu[WG2H + wa + 4], smu[WG2H + wb + 4] };
            uint32_t al[4] = { smu[WG2L + wa], smu[WG2L + wb],
                               smu[WG2L + wa + 4], smu[WG2L + wb + 4] };
            #pragma unroll
            for (int nt = 0; nt < 12; ++nt) {
                int c = h * 96 + nt * 8 + g;
                int wbb = c * 20 + kk * 8 + t;
                mma3(pacc[nt], ah, al, smu[WWTH + wbb], smu[WWTH + wbb + 4],
                     smu[WWTL + wbb], smu[WWTL + wbb + 4]);
            }
        }
        // store Q,K parts -> Ph
        #pragma unroll
        for (int nt = 0; nt < 8; ++nt) {
            uint32_t hu, lu;
            pack_hl(pacc[nt][0], pacc[nt][1], hu, lu);
            smu[WPHH + (m0 + g) * 36 + nt * 4 + t] = hu;
            smu[WPHL + (m0 + g) * 36 + nt * 4 + t] = lu;
            pack_hl(pacc[nt][2], pacc[nt][3], hu, lu);
            smu[WPHH + (m0 + g + 8) * 36 + nt * 4 + t] = hu;
            smu[WPHL + (m0 + g + 8) * 36 + nt * 4 + t] = lu;
        }
        // store C part transposed -> Ct[n][k]
        {
            __nv_bfloat16* cth = (__nv_bfloat16*)(smu + WCTH);
            __nv_bfloat16* ctl = (__nv_bfloat16*)(smu + WCTL);
            #pragma unroll
            for (int nt = 8; nt < 12; ++nt) {
                int j0 = (nt - 8) * 8 + 2 * t;
                #pragma unroll
                for (int b = 0; b < 2; ++b) {
                    float v0 = pacc[nt][b];         // row m0+g, col j0+b
                    float v1 = pacc[nt][2 + b];     // row m0+g+8
                    cth[(j0 + b) * 136 + m0 + g] = __float2bfloat16_rn(v0);
                    ctl[(j0 + b) * 136 + m0 + g] = __float2bfloat16_rn(v0 - bhi(v0));
                    cth[(j0 + b) * 136 + m0 + g + 8] = __float2bfloat16_rn(v1);
                    ctl[(j0 + b) * 136 + m0 + g + 8] = __float2bfloat16_rn(v1 - bhi(v1));
                }
            }
        }
        __syncthreads();

        // ======== GEMM_S: Q(rows m0..) @ K^T ========
        float sacc[16][4];
        #pragma unroll
        for (int a = 0; a < 16; ++a)
            #pragma unroll
            for (int b = 0; b < 4; ++b) sacc[a][b] = 0.f;
        #pragma unroll
        for (int kk = 0; kk < 2; ++kk) {
            int wa = (m0 + g) * 36 + kk * 8 + t;
            int wb = (m0 + g + 8) * 36 + kk * 8 + t;
            uint32_t ah[4] = { smu[WPHH + wa], smu[WPHH + wb],
                               smu[WPHH + wa + 4], smu[WPHH + wb + 4] };
            uint32_t al[4] = { smu[WPHL + wa], smu[WPHL + wb],
                               smu[WPHL + wa + 4], smu[WPHL + wb + 4] };
            #pragma unroll
            for (int nt = 0; nt < 16; ++nt) {
                int n = nt * 8 + g;
                int wbb = n * 36 + 16 + kk * 8 + t;
                mma3(sacc[nt], ah, al, smu[WPHH + wbb], smu[WPHH + wbb + 4],
                     smu[WPHL + wbb], smu[WPHL + wbb + 4]);
            }
        }

        // ======== softmax in registers (rows g, g+8 of warp tile) ========
        float mx[2] = { -3.0e38f, -3.0e38f };
        #pragma unroll
        for (int nt = 0; nt < 16; ++nt)
            #pragma unroll
            for (int b = 0; b < 2; ++b) {
                int col = nt * 8 + 2 * t + b;
                float4 hc = ((float4*)(smf + F_H2SW))[col];
                #pragma unroll
                for (int mt2 = 0; mt2 < 2; ++mt2) {
                    float v = sacc[nt][mt2 * 2 + b];
                    float h2d = fmaf(rH[mt2].x, hc.x, fmaf(rH[mt2].y, hc.y, rH[mt2].z * hc.z));
                    float lg = fmaf(v * INV_SQRT_D * h2d + ATTNW_SHIFT,
                                    rH[mt2].w * hc.w, -ATTNW_SHIFT);
                    sacc[nt][mt2 * 2 + b] = lg;
                    mx[mt2] = fmaxf(mx[mt2], lg);
                }
            }
        #pragma unroll
        for (int mt2 = 0; mt2 < 2; ++mt2) {
            mx[mt2] = fmaxf(mx[mt2], __shfl_xor_sync(0xffffffffu, mx[mt2], 1));
            mx[mt2] = fmaxf(mx[mt2], __shfl_xor_sync(0xffffffffu, mx[mt2], 2));
        }
        float ssum[2] = {}, ochp[2][3] = {};
        #pragma unroll
        for (int nt = 0; nt < 16; ++nt)
            #pragma unroll
            for (int b = 0; b < 2; ++b) {
                int col = nt * 8 + 2 * t + b;
                float4 hc = ((float4*)(smf + F_H2SW))[col];
                float smc = smf[F_SWM + col];
                #pragma unroll
                for (int mt2 = 0; mt2 < 2; ++mt2) {
                    float e = __expf(sacc[nt][mt2 * 2 + b] - mx[mt2]);
                    ssum[mt2] += e;
                    float h2d = fmaf(rH[mt2].x, hc.x, fmaf(rH[mt2].y, hc.y, rH[mt2].z * hc.z));
                    float ap = e * smc * h2d;
                    sacc[nt][mt2 * 2 + b] = ap;
                    ochp[mt2][0] = fmaf(ap, hc.x, ochp[mt2][0]);
                    ochp[mt2][1] = fmaf(ap, hc.y, ochp[mt2][1]);
                    ochp[mt2][2] = fmaf(ap, hc.z, ochp[mt2][2]);
                }
            }
        float rowscale[2];
        float wqh = smf[F_WEQ + h];
        #pragma unroll
        for (int mt2 = 0; mt2 < 2; ++mt2) {
            float s = ssum[mt2];
            s += __shfl_xor_sync(0xffffffffu, s, 1);
            s += __shfl_xor_sync(0xffffffffu, s, 2);
            rowscale[mt2] = rswm[mt2] / (s * SQRT3);
            float f = wqh * rowscale[mt2];
            och[mt2][0] = fmaf(f, ochp[mt2][0], och[mt2][0]);
            och[mt2][1] = fmaf(f, ochp[mt2][1], och[mt2][1]);
            och[mt2][2] = fmaf(f, ochp[mt2][2], och[mt2][2]);
        }
        // A' -> APR hi/lo (warp-private rows)
        #pragma unroll
        for (int nt = 0; nt < 16; ++nt)
            #pragma unroll
            for (int mt2 = 0; mt2 < 2; ++mt2) {
                int row = m0 + g + mt2 * 8;
                float a0 = sacc[nt][mt2 * 2] * rowscale[mt2];
                float a1 = sacc[nt][mt2 * 2 + 1] * rowscale[mt2];
                uint32_t hu, lu;
                pack_hl(a0, a1, hu, lu);
                smu[WAPH + row * 68 + nt * 4 + t] = hu;
                smu[WAPL + row * 68 + nt * 4 + t] = lu;
            }

        // ======== GEMM_O: oacc += A' @ C_h ========
        #pragma unroll
        for (int kk = 0; kk < 8; ++kk) {
            int wa = (m0 + g) * 68 + kk * 8 + t;
            int wb = (m0 + g + 8) * 68 + kk * 8 + t;
            uint32_t ah[4] = { smu[WAPH + wa], smu[WAPH + wb],
                               smu[WAPH + wa + 4], smu[WAPH + wb + 4] };
            uint32_t al[4] = { smu[WAPL + wa], smu[WAPL + wb],
                               smu[WAPL + wa + 4], smu[WAPL + wb + 4] };
            #pragma unroll
            for (int nt = 0; nt < 4; ++nt) {
                int n = nt * 8 + g;
                int wbb = n * 68 + kk * 8 + t;
                mma3(oacc[nt], ah, al, smu[WCTH + wbb], smu[WCTH + wbb + 4],
                     smu[WCTL + wbb], smu[WCTL + wbb + 4]);
            }
        }
        __syncthreads();   // Ph/Ct reused next head
    }

    // ---- outputs ----
    #pragma unroll
    for (int hb = 0; hb < 2; ++hb) {
        int row = m0 + g + hb * 8;
        float* go = outg + ((size_t)loc * 128 + row) * 32;
        #pragma unroll
        for (int nt = 0; nt < 4; ++nt) {
            int col = nt * 8 + 2 * t;
            float2 v = make_float2(oacc[nt][hb * 2] + smf[F_BH + col],
                                   oacc[nt][hb * 2 + 1] + smf[F_BH + col + 1]);
            *(float2*)(go + col) = v;
        }
    }
    if (outh) {
        #pragma unroll
        for (int mt2 = 0; mt2 < 2; ++mt2) {
            #pragma unroll
            for (int c = 0; c < 3; ++c) {
                och[mt2][c] += __shfl_xor_sync(0xffffffffu, och[mt2][c], 1);
                och[mt2][c] += __shfl_xor_sync(0xffffffffu, och[mt2][c], 2);
            }
            if (t == 0) {
                int row = m0 + g + mt2 * 8;
                float* ho = outh + ((size_t)loc * 128 + row) * 3;
                ho[0] = och[mt2][0]; ho[1] = och[mt2][1]; ho[2] = och[mt2][2];
            }
        }
    }
}

extern "C" void kernel_launch(void* const* d_in, const int* in_sizes, int n_in,
                              void* d_out, int out_size) {
    const float* g2  = (const float*)d_in[0];
    const float* h2  = (const float*)d_in[1];
    const float* sw  = (const float*)d_in[2];
    const float* wqk = (const float*)d_in[3];
    const float* wv  = (const float*)d_in[4];
    const float* wh  = (const float*)d_in[5];
    const float* bh  = (const float*)d_in[6];
    const float* weq = (const float*)d_in[7];
    const int*   msk = (const int*)d_in[8];

    int nloc = in_sizes[2] / 128;
    float* outg = (float*)d_out;
    size_t gsz = (size_t)nloc * 128 * 32;
    float* outh = ((size_t)out_size >= gsz + (size_t)nloc * 128 * 3) ? outg + gsz : nullptr;

    cudaFuncSetAttribute(rep_bf16_kernel, cudaFuncAttributeMaxDynamicSharedMemorySize, SMEM_BYTES);
    rep_bf16_kernel<<<nloc, THREADS, SMEM_BYTES>>>(g2, h2, sw, wqk, wv, wh, bh, weq, msk, outg, outh);
}

// round 11
// speedup vs baseline: 3.5009x; 1.1154x over previous
#include <cuda_runtime.h>
#include <cuda_bf16.h>
#include <cstdint>

#define THREADS 256
#define ATTNW_SHIFT 20.0f
#define INV_SQRT_D  0.17677669529663687f
#define SQRT3       1.7320508075688772f
#define SQRT32      5.656854249492381f
#define L2E         1.4426950408889634f

// word(=float)-index smem layout. bf16 arrays accessed as u32 words (2 elems).
#define WG2H  0        // 128*20
#define WG2L  2560
#define WWTH  5120     // 384*20
#define WWTL  12800
#define WPHH  20480    // 128*36
#define WPHL  25088
#define WCTH  29696    // 32*68
#define WCTL  31872
#define WAPH  34048    // 128*68
#define WAPL  42752
#define F_H2SW 51456
#define F_SWM  51968
#define F_BH   52096
#define F_WEQ  52128
#define SMEM_BYTES 208640
// init-only raw-weight scratch overlays APR region:
#define F_RQK  34048
#define F_RWV  42240
#define F_RWH  46336

static __device__ __forceinline__ uint32_t smem_u32(const void* p) {
    uint32_t a;
    asm("{ .reg .u64 t; cvta.to.shared.u64 t, %1; cvt.u32.u64 %0, t; }" : "=r"(a) : "l"(p));
    return a;
}
static __device__ __forceinline__ uint32_t packb(float e0, float e1) {
    uint32_t r;
    asm("cvt.rn.bf16x2.f32 %0, %1, %2;" : "=r"(r) : "f"(e1), "f"(e0));
    return r;
}
static __device__ __forceinline__ float bhi(float v) {
    return __bfloat162float(__float2bfloat16_rn(v));
}
static __device__ __forceinline__ void pack_hl(float v0, float v1,
                                               uint32_t& h, uint32_t& l) {
    h = packb(v0, v1);
    float h0 = __uint_as_float(h << 16);
    float h1 = __uint_as_float(h & 0xFFFF0000u);
    l = packb(v0 - h0, v1 - h1);
}
static __device__ __forceinline__ float ex2a(float x) {
    float r; asm("ex2.approx.f32 %0, %1;" : "=f"(r) : "f"(x)); return r;
}
static __device__ __forceinline__ void mma16(float* d, uint32_t a0, uint32_t a1,
                                             uint32_t a2, uint32_t a3,
                                             uint32_t b0, uint32_t b1) {
    asm volatile("mma.sync.aligned.m16n8k16.row.col.f32.bf16.bf16.f32 "
                 "{%0,%1,%2,%3}, {%4,%5,%6,%7}, {%8,%9}, {%0,%1,%2,%3};"
                 : "+f"(d[0]), "+f"(d[1]), "+f"(d[2]), "+f"(d[3])
                 : "r"(a0), "r"(a1), "r"(a2), "r"(a3), "r"(b0), "r"(b1));
}
static __device__ __forceinline__ void mma3(float* d, const uint32_t* ah,
                                            const uint32_t* al,
                                            uint32_t bh0, uint32_t bh1,
                                            uint32_t bl0, uint32_t bl1) {
    mma16(d, ah[0], ah[1], ah[2], ah[3], bh0, bh1);
    mma16(d, al[0], al[1], al[2], al[3], bh0, bh1);
    mma16(d, ah[0], ah[1], ah[2], ah[3], bl0, bl1);
}
#define LDSM4(r, ba) \
    asm volatile("ldmatrix.sync.aligned.m8n8.x4.shared.b16 {%0,%1,%2,%3}, [%4];" \
                 : "=r"((r)[0]), "=r"((r)[1]), "=r"((r)[2]), "=r"((r)[3]) : "r"(ba))
#define STSM4(ba, r0, r1, r2, r3) \
    asm volatile("stmatrix.sync.aligned.m8n8.x4.shared.b16 [%0], {%1,%2,%3,%4};" \
                 :: "r"(ba), "r"(r0), "r"(r1), "r"(r2), "r"(r3))
#define STSM2T(ba, r0, r1) \
    asm volatile("stmatrix.sync.aligned.m8n8.x2.trans.shared.b16 [%0], {%1,%2};" \
                 :: "r"(ba), "r"(r0), "r"(r1))

__global__ void __launch_bounds__(THREADS, 1)
rep_bf16_kernel(const float* __restrict__ g2, const float* __restrict__ h2,
                const float* __restrict__ sw, const float* __restrict__ wqk,
                const float* __restrict__ wv, const float* __restrict__ wh,
                const float* __restrict__ bh, const float* __restrict__ weq,
                const int* __restrict__ mask, float* __restrict__ outg,
                float* __restrict__ outh)
{
    extern __shared__ __align__(16) float smf[];
    uint32_t* smu = (uint32_t*)smf;
    const uint32_t sb = smem_u32(smf);
    const int tid = threadIdx.x, w = tid >> 5, lane = tid & 31;
    const int g = lane >> 2, t = lane & 3;
    const int m0 = w * 16;
    const int loc = blockIdx.x;
    // ldmatrix/stmatrix lane roles
    const int r8 = lane & 7, s01 = (lane >> 3) & 1, s2 = lane >> 4;

    const float* g2l = g2 + (size_t)loc * 128 * 32;
    const float* h2l = h2 + (size_t)loc * 128 * 3;
    const float* swl = sw + (size_t)loc * 128;
    const int*   ml  = mask + (size_t)loc * 128;

    // ---- stage raw weights ----
    {
        const float4* s1 = (const float4*)wqk;
        float4* d1 = (float4*)(smf + F_RQK);
        #pragma unroll
        for (int i = 0; i < 8; ++i) d1[tid + i * 256] = s1[tid + i * 256];
        const float4* s2p = (const float4*)wv;
        float4* d2 = (float4*)(smf + F_RWV);
        #pragma unroll
        for (int i = 0; i < 4; ++i) d2[tid + i * 256] = s2p[tid + i * 256];
        const float4* s3 = (const float4*)wh;
        float4* d3 = (float4*)(smf + F_RWH);
        #pragma unroll
        for (int i = 0; i < 4; ++i) d3[tid + i * 256] = s3[tid + i * 256];
    }
    // ---- g2 -> bf16 hi/lo (thread = half row) ----
    {
        int r = tid >> 1, hf = tid & 1;
        const float* src = g2l + (size_t)r * 32 + hf * 16;
        float e[16];
        #pragma unroll
        for (int i = 0; i < 4; ++i) {
            float4 v = ((const float4*)src)[i];
            e[4*i] = v.x; e[4*i+1] = v.y; e[4*i+2] = v.z; e[4*i+3] = v.w;
        }
        #pragma unroll
        for (int j = 0; j < 8; ++j) {
            uint32_t hu, lu;
            pack_hl(e[2*j], e[2*j+1], hu, lu);
            smu[WG2H + r * 20 + hf * 8 + j] = hu;
            smu[WG2L + r * 20 + hf * 8 + j] = lu;
        }
    }
    if (tid < 128) {
        float a = h2l[tid * 3], b = h2l[tid * 3 + 1], c = h2l[tid * 3 + 2];
        float sv = swl[tid];
        ((float4*)(smf + F_H2SW))[tid] = make_float4(a, b, c, sv);
        smf[F_SWM + tid] = ml[tid] ? sv : 0.0f;
    }
    if (tid < 32) smf[F_BH + tid] = bh[tid];
    if (tid < 4)  smf[F_WEQ + tid] = weq[tid];
    __syncthreads();

    // ---- WallT Q/K rows ----
    #pragma unroll 4
    for (int i = tid; i < 4096; i += THREADS) {
        int rqk = i >> 4, j = i & 15;
        int hh = rqk >> 6, r = rqk & 63;
        int c = hh * 96 + r;
        int src = (r < 32) ? r * 8 + hh : (r - 32) * 8 + 4 + hh;
        float v0 = smf[F_RQK + (2 * j) * 256 + src];
        float v1 = smf[F_RQK + (2 * j + 1) * 256 + src];
        uint32_t hu, lu;
        pack_hl(v0, v1, hu, lu);
        smu[WWTH + c * 20 + j] = hu;
        smu[WWTL + c * 20 + j] = lu;
    }
    // ---- WallT C rows: wc = wv @ wh folded per head ----
    if (tid < 128) {
        int hh = tid >> 5, m = tid & 31;
        float whcol[32];
        #pragma unroll 8
        for (int gg = 0; gg < 32; ++gg)
            whcol[gg] = smf[F_RWH + (gg * 4 + hh) * 32 + m];
        float acc[32];
        #pragma unroll 1
        for (int k = 0; k < 32; ++k) {
            const float* wvr = smf + F_RWV + k * 128 + hh;
            float s = 0.f;
            #pragma unroll
            for (int gg = 0; gg < 32; ++gg) s = fmaf(wvr[gg * 4], whcol[gg], s);
            acc[k] = s;
        }
        int c = hh * 96 + 64 + m;
        #pragma unroll
        for (int j = 0; j < 16; ++j) {
            uint32_t hu, lu;
            pack_hl(acc[2 * j], acc[2 * j + 1], hu, lu);
            smu[WWTH + c * 20 + j] = hu;
            smu[WWTL + c * 20 + j] = lu;
        }
    }
    __syncthreads();

    // ---- persistent state ----
    float oacc[4][4];
    #pragma unroll
    for (int a = 0; a < 4; ++a)
        #pragma unroll
        for (int b = 0; b < 4; ++b) oacc[a][b] = 0.f;
    float och[2][3] = {};
    float4 rH[2]; float rswm[2], rh2I[2][3], rwL[2];
    #pragma unroll
    for (int mt2 = 0; mt2 < 2; ++mt2) {
        int row = m0 + g + mt2 * 8;
        rH[mt2] = ((float4*)(smf + F_H2SW))[row];
        rswm[mt2] = smf[F_SWM + row];
        rh2I[mt2][0] = rH[mt2].x * INV_SQRT_D;
        rh2I[mt2][1] = rH[mt2].y * INV_SQRT_D;
        rh2I[mt2][2] = rH[mt2].z * INV_SQRT_D;
        rwL[mt2] = rH[mt2].w * L2E;
    }

    // precomputed lane-address bases (byte addrs)
    const int arow = m0 + r8 + s01 * 8;            // A-frag / stm row
    const uint32_t aG2h = sb + 4 * (WG2H + arow * 20 + s2 * 4);
    const uint32_t aG2l = sb + 4 * (WG2L + arow * 20 + s2 * 4);
    const uint32_t aPHh = sb + 4 * (WPHH + arow * 36 + s2 * 4);
    const uint32_t aPHl = sb + 4 * (WPHL + arow * 36 + s2 * 4);
    const uint32_t aAPh = sb + 4 * (WAPH + arow * 68 + s2 * 4);
    const uint32_t aAPl = sb + 4 * (WAPL + arow * 68 + s2 * 4);
    const int bnrow = r8 + s2 * 8;                 // B-frag row-in-group
    const uint32_t stPH = sb + 4 * (WPHH + arow * 36 + s2 * 4);   // stm x4 Ph
    const uint32_t stAP = sb + 4 * (WAPH + arow * 68 + s2 * 4);   // stm x4 A'
    const uint32_t stCT = sb + 4 * (WCTH + (lane & 7) * 68 + w * 8 + ((lane >> 3) & 1) * 4);
    const float C50 = -50.0f * L2E;

    #pragma unroll 1
    for (int h = 0; h < 4; ++h) {
        // ======== GEMM_P ========
        float pacc[12][4];
        #pragma unroll
        for (int a = 0; a < 12; ++a)
            #pragma unroll
            for (int b = 0; b < 4; ++b) pacc[a][b] = 0.f;
        #pragma unroll
        for (int kk = 0; kk < 2; ++kk) {
            uint32_t ah[4], al[4];
            LDSM4(ah, aG2h + 32 * kk);
            LDSM4(al, aG2l + 32 * kk);
            #pragma unroll
            for (int ntp = 0; ntp < 6; ++ntp) {
                int n = h * 96 + ntp * 16 + bnrow;
                uint32_t bb = sb + 4 * (WWTH + n * 20 + kk * 8 + s01 * 4);
                uint32_t bhr[4], blr[4];
                LDSM4(bhr, bb);
                LDSM4(blr, bb + 4 * (WWTL - WWTH));
                mma3(pacc[2*ntp],   ah, al, bhr[0], bhr[1], blr[0], blr[1]);
                mma3(pacc[2*ntp+1], ah, al, bhr[2], bhr[3], blr[2], blr[3]);
            }
        }
        // store Q,K -> Ph via stmatrix.x4 (hi/lo)
        #pragma unroll
        for (int ntp = 0; ntp < 4; ++ntp) {
            uint32_t h0, l0, h1, l1, h2r, l2, h3, l3;
            pack_hl(pacc[2*ntp][0],   pacc[2*ntp][1],   h0, l0);
            pack_hl(pacc[2*ntp][2],   pacc[2*ntp][3],   h1, l1);
            pack_hl(pacc[2*ntp+1][0], pacc[2*ntp+1][1], h2r, l2);
            pack_hl(pacc[2*ntp+1][2], pacc[2*ntp+1][3], h3, l3);
            STSM4(stPH + 32 * ntp, h0, h1, h2r, h3);
            STSM4(stPH + 32 * ntp + 4 * (WPHL - WPHH), l0, l1, l2, l3);
        }
        // store C transposed -> Ct via stmatrix.x2.trans (hi/lo)
        #pragma unroll
        for (int nt = 8; nt < 12; ++nt) {
            int j0 = (nt - 8) * 8;
            uint32_t h0, l0, h1, l1;
            pack_hl(pacc[nt][0], pacc[nt][1], h0, l0);
            pack_hl(pacc[nt][2], pacc[nt][3], h1, l1);
            uint32_t ba = stCT + 4 * (j0 * 68);
            STSM2T(ba, h0, h1);
            STSM2T(ba + 4 * (WCTL - WCTH), l0, l1);
        }
        __syncthreads();

        // ======== GEMM_S ========
        float sacc[16][4];
        #pragma unroll
        for (int a = 0; a < 16; ++a)
            #pragma unroll
            for (int b = 0; b < 4; ++b) sacc[a][b] = 0.f;
        #pragma unroll
        for (int kk = 0; kk < 2; ++kk) {
            uint32_t ah[4], al[4];
            LDSM4(ah, aPHh + 32 * kk);
            LDSM4(al, aPHl + 32 * kk);
            #pragma unroll
            for (int ntp = 0; ntp < 8; ++ntp) {
                int n = ntp * 16 + bnrow;
                uint32_t bb = sb + 4 * (WPHH + n * 36 + 16 + kk * 8 + s01 * 4);
                uint32_t bhr[4], blr[4];
                LDSM4(bhr, bb);
                LDSM4(blr, bb + 4 * (WPHL - WPHH));
                mma3(sacc[2*ntp],   ah, al, bhr[0], bhr[1], blr[0], blr[1]);
                mma3(sacc[2*ntp+1], ah, al, bhr[2], bhr[3], blr[2], blr[3]);
            }
        }

        // ======== single-pass softmax (fixed shift 30) ========
        float ssum[2] = {0.f, 0.f}, ochp[2][3] = {};
        #pragma unroll
        for (int nt = 0; nt < 16; ++nt)
            #pragma unroll
            for (int b = 0; b < 2; ++b) {
                int col = nt * 8 + 2 * t + b;
                float4 hc = ((float4*)(smf + F_H2SW))[col];
                float smc = smf[F_SWM + col];
                #pragma unroll
                for (int mt2 = 0; mt2 < 2; ++mt2) {
                    float dot = sacc[nt][mt2 * 2 + b];
                    float h2dI = fmaf(rh2I[mt2][0], hc.x,
                               fmaf(rh2I[mt2][1], hc.y, rh2I[mt2][2] * hc.z));
                    float t1 = fmaf(dot, h2dI, ATTNW_SHIFT);
                    float swwL = hc.w * rwL[mt2];
                    float e = ex2a(fmaf(t1, swwL, C50));
                    ssum[mt2] += e;
                    float ap = (e * smc) * h2dI;
                    sacc[nt][mt2 * 2 + b] = ap;
                    ochp[mt2][0] = fmaf(ap, hc.x, ochp[mt2][0]);
                    ochp[mt2][1] = fmaf(ap, hc.y, ochp[mt2][1]);
                    ochp[mt2][2] = fmaf(ap, hc.z, ochp[mt2][2]);
                }
            }
        float rowscale[2];
        float wqh = smf[F_WEQ + h];
        #pragma unroll
        for (int mt2 = 0; mt2 < 2; ++mt2) {
            float s = ssum[mt2];
            s += __shfl_xor_sync(0xffffffffu, s, 1);
            s += __shfl_xor_sync(0xffffffffu, s, 2);
            rowscale[mt2] = rswm[mt2] * SQRT32 / (fmaxf(s, 1e-30f) * SQRT3);
            float f = wqh * rowscale[mt2];
            och[mt2][0] = fmaf(f, ochp[mt2][0], och[mt2][0]);
            och[mt2][1] = fmaf(f, ochp[mt2][1], och[mt2][1]);
            och[mt2][2] = fmaf(f, ochp[mt2][2], och[mt2][2]);
        }
        // A' -> APR hi/lo via stmatrix.x4 (warp-private rows)
        #pragma unroll
        for (int ntp = 0; ntp < 8; ++ntp) {
            uint32_t h0, l0, h1, l1, h2r, l2, h3, l3;
            pack_hl(sacc[2*ntp][0]   * rowscale[0], sacc[2*ntp][1]   * rowscale[0], h0, l0);
            pack_hl(sacc[2*ntp][2]   * rowscale[1], sacc[2*ntp][3]   * rowscale[1], h1, l1);
            pack_hl(sacc[2*ntp+1][0] * rowscale[0], sacc[2*ntp+1][1] * rowscale[0], h2r, l2);
            pack_hl(sacc[2*ntp+1][2] * rowscale[1], sacc[2*ntp+1][3] * rowscale[1], h3, l3);
            STSM4(stAP + 32 * ntp, h0, h1, h2r, h3);
            STSM4(stAP + 32 * ntp + 4 * (WAPL - WAPH), l0, l1, l2, l3);
        }
        __syncwarp();

        // ======== GEMM_O: oacc += A' @ C_h ========
        #pragma unroll 2
        for (int kk = 0; kk < 8; ++kk) {
            uint32_t ah[4], al[4];
            LDSM4(ah, aAPh + 32 * kk);
            LDSM4(al, aAPl + 32 * kk);
            #pragma unroll
            for (int ntp = 0; ntp < 2; ++ntp) {
                int n = ntp * 16 + bnrow;
                uint32_t bb = sb + 4 * (WCTH + n * 68 + kk * 8 + s01 * 4);
                uint32_t bhr[4], blr[4];
                LDSM4(bhr, bb);
                LDSM4(blr, bb + 4 * (WCTL - WCTH));
                mma3(oacc[2*ntp],   ah, al, bhr[0], bhr[1], blr[0], blr[1]);
                mma3(oacc[2*ntp+1], ah, al, bhr[2], bhr[3], blr[2], blr[3]);
            }
        }
        __syncthreads();   // Ph/Ct reused next head
    }

    // ---- outputs ----
    #pragma unroll
    for (int hb = 0; hb < 2; ++hb) {
        int row = m0 + g + hb * 8;
        float* go = outg + ((size_t)loc * 128 + row) * 32;
        #pragma unroll
        for (int nt = 0; nt < 4; ++nt) {
            int col = nt * 8 + 2 * t;
            float2 v = make_float2(oacc[nt][hb * 2] + smf[F_BH + col],
                                   oacc[nt][hb * 2 + 1] + smf[F_BH + col + 1]);
            *(float2*)(go + col) = v;
        }
    }
    if (outh) {
        #pragma unroll
        for (int mt2 = 0; mt2 < 2; ++mt2) {
            #pragma unroll
            for (int c = 0; c < 3; ++c) {
                och[mt2][c] += __shfl_xor_sync(0xffffffffu, och[mt2][c], 1);
                och[mt2][c] += __shfl_xor_sync(0xffffffffu, och[mt2][c], 2);
            }
            if (t == 0) {
                int row = m0 + g + mt2 * 8;
                float* ho = outh + ((size_t)loc * 128 + row) * 3;
                ho[0] = och[mt2][0]; ho[1] = och[mt2][1]; ho[2] = och[mt2][2];
            }
        }
    }
}

extern "C" void kernel_launch(void* const* d_in, const int* in_sizes, int n_in,
                              void* d_out, int out_size) {
    const float* g2  = (const float*)d_in[0];
    const float* h2  = (const float*)d_in[1];
    const float* sw  = (const float*)d_in[2];
    const float* wqk = (const float*)d_in[3];
    const float* wv  = (const float*)d_in[4];
    const float* wh  = (const float*)d_in[5];
    const float* bh  = (const float*)d_in[6];
    const float* weq = (const float*)d_in[7];
    const int*   msk = (const int*)d_in[8];

    int nloc = in_sizes[2] / 128;
    float* outg = (float*)d_out;
    size_t gsz = (size_t)nloc * 128 * 32;
    float* outh = ((size_t)out_size >= gsz + (size_t)nloc * 128 * 3) ? outg + gsz : nullptr;

    cudaFuncSetAttribute(rep_bf16_kernel, cudaFuncAttributeMaxDynamicSharedMemorySize, SMEM_BYTES);
    rep_bf16_kernel<<<nloc, THREADS, SMEM_BYTES>>>(g2, h2, sw, wqk, wv, wh, bh, weq, msk, outg, outh);
}